// round 1
// baseline (speedup 1.0000x reference)
#include <cuda_runtime.h>

// Problem constants
#define CAP_A   32
#define CAP_B   32
#define KK      3
#define PDIM    4
#define PSIZE   16            // PDIM*PDIM
#define STRIDE  2
#define ITERS   3
#define OH      15
#define OW      15
#define NBATCH  2
#define NPOS    (NBATCH*OH*OW)   // 450
#define KKA     (KK*KK*CAP_A)    // 288
#define EPS_SQ  1e-8f
#define NWARPS  9                // 288 threads

// One block per (n, j). Thread t owns routing input capsule i = t.
// v_i (16 floats) lives in registers for the whole routing loop.
__global__ __launch_bounds__(KKA) void caps_fused_kernel(
    const float* __restrict__ x,     // (2, 32, 32, 512)
    const float* __restrict__ w,     // (288, 32, 4, 4)
    float* __restrict__ out)         // (2, 15, 15, 512)
{
    const int bid = blockIdx.x;
    const int j   = bid & 31;        // output capsule
    const int n   = bid >> 5;        // position index
    const int b   = n / (OH * OW);
    const int rem = n % (OH * OW);
    const int oy  = rem / OW;
    const int ox  = rem % OW;

    const int tid  = threadIdx.x;    // = i in [0, 288)
    const int lane = tid & 31;
    const int warp = tid >> 5;       // 0..8

    __shared__ float sm_warp[NWARPS * 16];  // per-warp partial 16-vectors
    __shared__ float sm_scalar[NWARPS];     // per-warp scalar partials
    __shared__ float sm_p[16];              // current pooled/squashed capsule
    __shared__ float sm_bcast;              // scalar broadcast

    // decompose i -> (ky, kx, a)
    const int ky = tid / (KK * CAP_A);       // /96
    const int kx = (tid / CAP_A) % KK;
    const int a  = tid % CAP_A;

    // ---- load x patch row (16 floats) and weight (16 floats) ----
    const float* xp = x + ((size_t)((b * 32 + (oy * STRIDE + ky)) * 32
                                    + (ox * STRIDE + kx)) * 512 + a * PSIZE);
    const float* wp = w + ((size_t)tid * CAP_B + j) * PSIZE;

    float xm[16], wm[16];
#pragma unroll
    for (int t = 0; t < 4; t++) {
        reinterpret_cast<float4*>(xm)[t] = reinterpret_cast<const float4*>(xp)[t];
        reinterpret_cast<float4*>(wm)[t] = reinterpret_cast<const float4*>(wp)[t];
    }

    // ---- v[i] = x_i (4x4) @ w_ij (4x4), kept in registers ----
    float v[16];
#pragma unroll
    for (int p = 0; p < 4; p++) {
#pragma unroll
        for (int q = 0; q < 4; q++) {
            float acc = 0.f;
#pragma unroll
            for (int r = 0; r < 4; r++)
                acc = fmaf(xm[p * 4 + r], wm[r * 4 + q], acc);
            v[p * 4 + q] = acc;
        }
    }

    // ---- dynamic routing ----
    float logit = 0.f;

    for (int it = 0; it < ITERS; it++) {
        // --- softmax over i (288) ---
        // max
        float m = logit;
#pragma unroll
        for (int off = 16; off >= 1; off >>= 1)
            m = fmaxf(m, __shfl_xor_sync(0xffffffffu, m, off));
        if (lane == 0) sm_scalar[warp] = m;
        __syncthreads();
        if (tid == 0) {
            float mm = sm_scalar[0];
#pragma unroll
            for (int wi = 1; wi < NWARPS; wi++) mm = fmaxf(mm, sm_scalar[wi]);
            sm_bcast = mm;
        }
        __syncthreads();
        m = sm_bcast;
        float e = __expf(logit - m);
        // sum
        float z = e;
#pragma unroll
        for (int off = 16; off >= 1; off >>= 1)
            z += __shfl_xor_sync(0xffffffffu, z, off);
        if (lane == 0) sm_scalar[warp] = z;
        __syncthreads();
        if (tid == 0) {
            float zz = 0.f;
#pragma unroll
            for (int wi = 0; wi < NWARPS; wi++) zz += sm_scalar[wi];
            sm_bcast = zz;
        }
        __syncthreads();
        const float r = e / sm_bcast;

        // --- s[16] = sum_i r_i * v_i : warp butterfly + cross-warp combine ---
#pragma unroll
        for (int q = 0; q < 16; q++) {
            float sv = r * v[q];
#pragma unroll
            for (int off = 16; off >= 1; off >>= 1)
                sv += __shfl_xor_sync(0xffffffffu, sv, off);
            if (lane == 0) sm_warp[warp * 16 + q] = sv;
        }
        __syncthreads();

        // --- squash on lanes 0..15 of warp 0 ---
        if (tid < 16) {
            float sq = 0.f;
#pragma unroll
            for (int wi = 0; wi < NWARPS; wi++) sq += sm_warp[wi * 16 + tid];
            float n2p = sq * sq;
#pragma unroll
            for (int off = 8; off >= 1; off >>= 1)
                n2p += __shfl_xor_sync(0x0000ffffu, n2p, off);
            const float n2 = n2p;
            const float scale = n2 / (1.f + n2) * rsqrtf(n2 + EPS_SQ);
            sm_p[tid] = sq * scale;
        }
        __syncthreads();

        // --- agreement update ---
        if (it < ITERS - 1) {
            float d = 0.f;
#pragma unroll
            for (int q = 0; q < 16; q++)
                d = fmaf(v[q], sm_p[q], d);
            logit += d;
        }
    }

    // ---- write output: out[n, j*16 + q] ----
    if (tid < 16)
        out[(size_t)n * (CAP_B * PSIZE) + j * PSIZE + tid] = sm_p[tid];
}

extern "C" void kernel_launch(void* const* d_in, const int* in_sizes, int n_in,
                              void* d_out, int out_size) {
    (void)in_sizes; (void)n_in; (void)out_size;
    const float* x = (const float*)d_in[0];        // (2,32,32,512)
    const float* w = (const float*)d_in[1];        // (288,32,4,4)
    float* out = (float*)d_out;                    // (2,15,15,512)

    dim3 grid(NPOS * CAP_B);   // 14400 blocks, j fastest (same-n blocks adjacent)
    dim3 block(KKA);           // 288 threads
    caps_fused_kernel<<<grid, block>>>(x, w, out);
}

// round 2
// speedup vs baseline: 1.5042x; 1.5042x over previous
#include <cuda_runtime.h>

// Problem constants
#define CAP_A   32
#define CAP_B   32
#define KK      3
#define PSIZE   16
#define STRIDE  2
#define OH      15
#define OW      15
#define NBATCH  2
#define NPOS    (NBATCH*OH*OW)   // 450
#define KKA     (KK*KK*CAP_A)    // 288
#define EPS_SQ  1e-8f
#define NWARPS  9

// Butterfly vector-exchange reduction: 32 lanes each hold t[0..15];
// afterwards lane l holds sum over all lanes of component (l & 15).
// Cost: 16 + 8 + 4 + 2 + 1 = 31 shuffles (vs 80 for per-component trees).
__device__ __forceinline__ void vec_reduce16(float t[16], int lane) {
#pragma unroll
    for (int k = 0; k < 16; k++)
        t[k] += __shfl_xor_sync(0xffffffffu, t[k], 16);
    {
        const bool hi = lane & 8;
#pragma unroll
        for (int k = 0; k < 8; k++) {
            float keep = hi ? t[k + 8] : t[k];
            float send = hi ? t[k]     : t[k + 8];
            t[k] = keep + __shfl_xor_sync(0xffffffffu, send, 8);
        }
    }
    {
        const bool hi = lane & 4;
#pragma unroll
        for (int k = 0; k < 4; k++) {
            float keep = hi ? t[k + 4] : t[k];
            float send = hi ? t[k]     : t[k + 4];
            t[k] = keep + __shfl_xor_sync(0xffffffffu, send, 4);
        }
    }
    {
        const bool hi = lane & 2;
#pragma unroll
        for (int k = 0; k < 2; k++) {
            float keep = hi ? t[k + 2] : t[k];
            float send = hi ? t[k]     : t[k + 2];
            t[k] = keep + __shfl_xor_sync(0xffffffffu, send, 2);
        }
    }
    {
        const bool hi = lane & 1;
        float keep = hi ? t[1] : t[0];
        float send = hi ? t[0] : t[1];
        t[0] = keep + __shfl_xor_sync(0xffffffffu, send, 1);
    }
}

// Pool r_i*v_i over the block, squash, publish p[16] to sm_p.
// t[] is destroyed. Two syncthreads.
__device__ __forceinline__ void pool_squash(float t[16], int tid, int lane, int warp,
                                            float* sm_warp, float* sm_p) {
    vec_reduce16(t, lane);
    if (lane < 16) sm_warp[warp * 16 + lane] = t[0];
    __syncthreads();
    if (tid < 16) {
        float s = sm_warp[tid];
#pragma unroll
        for (int w = 1; w < NWARPS; w++) s += sm_warp[w * 16 + tid];
        float n2 = s * s;
#pragma unroll
        for (int off = 8; off >= 1; off >>= 1)
            n2 += __shfl_xor_sync(0x0000ffffu, n2, off);
        const float scale = n2 / (1.f + n2) * rsqrtf(n2 + EPS_SQ);
        sm_p[tid] = s * scale;
    }
    __syncthreads();
}

// Block softmax over 288 logits with per-warp local normalization.
// One syncthreads; no serialized single-thread phase.
__device__ __forceinline__ float softmax_r(float logit, int lane, int warp,
                                           float* sm_m, float* sm_z) {
    float m = logit;
#pragma unroll
    for (int off = 16; off >= 1; off >>= 1)
        m = fmaxf(m, __shfl_xor_sync(0xffffffffu, m, off));
    const float e = __expf(logit - m);
    float z = e;
#pragma unroll
    for (int off = 16; off >= 1; off >>= 1)
        z += __shfl_xor_sync(0xffffffffu, z, off);
    if (lane == 0) { sm_m[warp] = m; sm_z[warp] = z; }
    __syncthreads();
    float M = sm_m[0];
#pragma unroll
    for (int w = 1; w < NWARPS; w++) M = fmaxf(M, sm_m[w]);
    float Z = 0.f;
#pragma unroll
    for (int w = 0; w < NWARPS; w++) Z += sm_z[w] * __expf(sm_m[w] - M);
    return e * __expf(m - M) / Z;
}

__global__ __launch_bounds__(KKA) void caps_fused_kernel(
    const float* __restrict__ x,     // (2, 32, 32, 512)
    const float* __restrict__ w,     // (288, 32, 4, 4)
    float* __restrict__ out)         // (2, 15, 15, 512)
{
    const int bid = blockIdx.x;
    const int j   = bid & 31;
    const int n   = bid >> 5;
    const int b   = n / (OH * OW);
    const int rem = n % (OH * OW);
    const int oy  = rem / OW;
    const int ox  = rem % OW;

    const int tid  = threadIdx.x;    // = i in [0, 288)
    const int lane = tid & 31;
    const int warp = tid >> 5;

    __shared__ float sm_warp[NWARPS * 16];
    __shared__ float sm_m[NWARPS];
    __shared__ float sm_z[NWARPS];
    __shared__ float sm_p[16];

    const int ky = tid / (KK * CAP_A);
    const int kx = (tid / CAP_A) % KK;
    const int a  = tid % CAP_A;

    const float* xp = x + ((size_t)((b * 32 + (oy * STRIDE + ky)) * 32
                                    + (ox * STRIDE + kx)) * 512 + a * PSIZE);
    const float* wp = w + ((size_t)tid * CAP_B + j) * PSIZE;

    float xm[16], wm[16];
#pragma unroll
    for (int t4 = 0; t4 < 4; t4++) {
        reinterpret_cast<float4*>(xm)[t4] = reinterpret_cast<const float4*>(xp)[t4];
        reinterpret_cast<float4*>(wm)[t4] = reinterpret_cast<const float4*>(wp)[t4];
    }

    // v[i] = x_i (4x4) @ w_ij (4x4), register-resident
    float v[16];
#pragma unroll
    for (int p = 0; p < 4; p++)
#pragma unroll
        for (int q = 0; q < 4; q++) {
            float acc = 0.f;
#pragma unroll
            for (int r = 0; r < 4; r++)
                acc = fmaf(xm[p * 4 + r], wm[r * 4 + q], acc);
            v[p * 4 + q] = acc;
        }

    float t[16];

    // ---- iteration 0: logits are all zero -> r = 1/288 exactly ----
    const float r0 = 1.0f / (float)KKA;
#pragma unroll
    for (int q = 0; q < 16; q++) t[q] = v[q] * r0;
    pool_squash(t, tid, lane, warp, sm_warp, sm_p);

    float logit = 0.f;
#pragma unroll
    for (int q = 0; q < 16; q++) logit = fmaf(v[q], sm_p[q], logit);

    // ---- iteration 1 ----
    float r = softmax_r(logit, lane, warp, sm_m, sm_z);
#pragma unroll
    for (int q = 0; q < 16; q++) t[q] = v[q] * r;
    pool_squash(t, tid, lane, warp, sm_warp, sm_p);

#pragma unroll
    for (int q = 0; q < 16; q++) logit = fmaf(v[q], sm_p[q], logit);

    // ---- iteration 2 (final; no agreement update needed) ----
    r = softmax_r(logit, lane, warp, sm_m, sm_z);
#pragma unroll
    for (int q = 0; q < 16; q++) t[q] = v[q] * r;
    pool_squash(t, tid, lane, warp, sm_warp, sm_p);

    if (tid < 16)
        out[(size_t)n * (CAP_B * PSIZE) + j * PSIZE + tid] = sm_p[tid];
}

extern "C" void kernel_launch(void* const* d_in, const int* in_sizes, int n_in,
                              void* d_out, int out_size) {
    (void)in_sizes; (void)n_in; (void)out_size;
    const float* x = (const float*)d_in[0];
    const float* w = (const float*)d_in[1];
    float* out = (float*)d_out;

    dim3 grid(NPOS * CAP_B);   // 14400 blocks
    dim3 block(KKA);           // 288 threads
    caps_fused_kernel<<<grid, block>>>(x, w, out);
}

// round 3
// speedup vs baseline: 2.2240x; 1.4785x over previous
#include <cuda_runtime.h>

// Problem constants
#define CAP_A   32
#define CAP_B   32
#define KK      3
#define PSIZE   16
#define STRIDE  2
#define OH      15
#define OW      15
#define NBATCH  2
#define NPOS    (NBATCH*OH*OW)   // 450
#define KKA     (KK*KK*CAP_A)    // 288
#define EPS_SQ  1e-8f
#define NT      96               // threads per block
#define NWARPS  3
#define CPT     3                // capsules (i values) per thread

// Butterfly vector-exchange reduction: 32 lanes each hold t[0..15];
// afterwards lane l holds the lane-sum of component (l & 15).
// 16 + 8 + 4 + 2 + 1 = 31 shuffles.
__device__ __forceinline__ void vec_reduce16(float t[16], int lane) {
#pragma unroll
    for (int k = 0; k < 16; k++)
        t[k] += __shfl_xor_sync(0xffffffffu, t[k], 16);
    {
        const bool hi = lane & 8;
#pragma unroll
        for (int k = 0; k < 8; k++) {
            float keep = hi ? t[k + 8] : t[k];
            float send = hi ? t[k]     : t[k + 8];
            t[k] = keep + __shfl_xor_sync(0xffffffffu, send, 8);
        }
    }
    {
        const bool hi = lane & 4;
#pragma unroll
        for (int k = 0; k < 4; k++) {
            float keep = hi ? t[k + 4] : t[k];
            float send = hi ? t[k]     : t[k + 4];
            t[k] = keep + __shfl_xor_sync(0xffffffffu, send, 4);
        }
    }
    {
        const bool hi = lane & 2;
#pragma unroll
        for (int k = 0; k < 2; k++) {
            float keep = hi ? t[k + 2] : t[k];
            float send = hi ? t[k]     : t[k + 2];
            t[k] = keep + __shfl_xor_sync(0xffffffffu, send, 2);
        }
    }
    {
        const bool hi = lane & 1;
        float keep = hi ? t[1] : t[0];
        float send = hi ? t[0] : t[1];
        t[0] = keep + __shfl_xor_sync(0xffffffffu, send, 1);
    }
}

// Pool t over the block, squash, publish p[16] to sm_p. Destroys t.
__device__ __forceinline__ void pool_squash(float t[16], int tid, int lane, int warp,
                                            float* sm_warp, float* sm_p) {
    vec_reduce16(t, lane);
    if (lane < 16) sm_warp[warp * 16 + lane] = t[0];
    __syncthreads();
    if (tid < 16) {
        float s = sm_warp[tid] + sm_warp[16 + tid] + sm_warp[32 + tid];
        float n2 = s * s;
#pragma unroll
        for (int off = 8; off >= 1; off >>= 1)
            n2 += __shfl_xor_sync(0x0000ffffu, n2, off);
        const float scale = n2 / (1.f + n2) * rsqrtf(n2 + EPS_SQ);
        sm_p[tid] = s * scale;
    }
    __syncthreads();
}

__global__ __launch_bounds__(NT) void caps_fused_kernel(
    const float* __restrict__ x,     // (2, 32, 32, 512)
    const float* __restrict__ w,     // (288, 32, 4, 4)
    float* __restrict__ out)         // (2, 15, 15, 512)
{
    const int bid = blockIdx.x;
    const int j   = bid & 31;
    const int n   = bid >> 5;
    const int b   = n / (OH * OW);
    const int rem = n % (OH * OW);
    const int oy  = rem / OW;
    const int ox  = rem % OW;

    const int tid  = threadIdx.x;    // [0, 96)
    const int lane = tid & 31;       // = a
    const int warp = tid >> 5;       // = kx (0..2)

    __shared__ float sm_warp[NWARPS * 16];
    __shared__ float sm_m[NWARPS];
    __shared__ float sm_z[NWARPS];
    __shared__ float sm_p[16];

    // This thread owns i_c = tid + 96*c  (c = ky), all with kx=warp, a=lane.
    const float* xbase = x + ((size_t)((b * 32 + oy * STRIDE) * 32
                                       + (ox * STRIDE + warp)) * 512 + lane * PSIZE);
    const float* wbase = w + ((size_t)tid * CAP_B + j) * PSIZE;

    // v[c][16] register-resident
    float v[CPT][16];
#pragma unroll
    for (int c = 0; c < CPT; c++) {
        float xm[16], wm[16];
        const float* xp = xbase + (size_t)c * 32 * 512;            // ky = c
        const float* wp = wbase + (size_t)c * 96 * CAP_B * PSIZE;  // i += 96
#pragma unroll
        for (int t4 = 0; t4 < 4; t4++) {
            reinterpret_cast<float4*>(xm)[t4] = reinterpret_cast<const float4*>(xp)[t4];
            reinterpret_cast<float4*>(wm)[t4] = reinterpret_cast<const float4*>(wp)[t4];
        }
#pragma unroll
        for (int p = 0; p < 4; p++)
#pragma unroll
            for (int q = 0; q < 4; q++) {
                float acc = 0.f;
#pragma unroll
                for (int r = 0; r < 4; r++)
                    acc = fmaf(xm[p * 4 + r], wm[r * 4 + q], acc);
                v[c][p * 4 + q] = acc;
            }
    }

    float t[16];
    float logit[CPT] = {0.f, 0.f, 0.f};

    // ---- iteration 0: logits all zero -> r = 1/288 exactly ----
    const float r0 = 1.0f / (float)KKA;
#pragma unroll
    for (int q = 0; q < 16; q++)
        t[q] = (v[0][q] + v[1][q] + v[2][q]) * r0;
    pool_squash(t, tid, lane, warp, sm_warp, sm_p);

    float pq[16];
#pragma unroll
    for (int q = 0; q < 16; q++) pq[q] = sm_p[q];
#pragma unroll
    for (int c = 0; c < CPT; c++) {
        float d = 0.f;
#pragma unroll
        for (int q = 0; q < 16; q++) d = fmaf(v[c][q], pq[q], d);
        logit[c] += d;
    }

    // ---- iterations 1..2 ----
#pragma unroll
    for (int it = 1; it < 3; it++) {
        // block softmax over 288 logits (3 per thread, 3 warps)
        float m = fmaxf(logit[0], fmaxf(logit[1], logit[2]));
#pragma unroll
        for (int off = 16; off >= 1; off >>= 1)
            m = fmaxf(m, __shfl_xor_sync(0xffffffffu, m, off));
        float e[CPT];
        float z = 0.f;
#pragma unroll
        for (int c = 0; c < CPT; c++) { e[c] = __expf(logit[c] - m); z += e[c]; }
#pragma unroll
        for (int off = 16; off >= 1; off >>= 1)
            z += __shfl_xor_sync(0xffffffffu, z, off);
        if (lane == 0) { sm_m[warp] = m; sm_z[warp] = z; }
        __syncthreads();
        float M = fmaxf(sm_m[0], fmaxf(sm_m[1], sm_m[2]));
        float Z = sm_z[0] * __expf(sm_m[0] - M)
                + sm_z[1] * __expf(sm_m[1] - M)
                + sm_z[2] * __expf(sm_m[2] - M);
        const float f = __expf(m - M) / Z;   // r_c = e[c] * f

        // partial pool (pure FMA), then cross-lane reduce
#pragma unroll
        for (int q = 0; q < 16; q++) {
            float s = e[0] * v[0][q];
            s = fmaf(e[1], v[1][q], s);
            s = fmaf(e[2], v[2][q], s);
            t[q] = s * f;
        }
        pool_squash(t, tid, lane, warp, sm_warp, sm_p);

        if (it < 2) {
#pragma unroll
            for (int q = 0; q < 16; q++) pq[q] = sm_p[q];
#pragma unroll
            for (int c = 0; c < CPT; c++) {
                float d = 0.f;
#pragma unroll
                for (int q = 0; q < 16; q++) d = fmaf(v[c][q], pq[q], d);
                logit[c] += d;
            }
        }
    }

    if (tid < 16)
        out[(size_t)n * (CAP_B * PSIZE) + j * PSIZE + tid] = sm_p[tid];
}

extern "C" void kernel_launch(void* const* d_in, const int* in_sizes, int n_in,
                              void* d_out, int out_size) {
    (void)in_sizes; (void)n_in; (void)out_size;
    const float* x = (const float*)d_in[0];
    const float* w = (const float*)d_in[1];
    float* out = (float*)d_out;

    dim3 grid(NPOS * CAP_B);   // 14400 blocks
    dim3 block(NT);            // 96 threads
    caps_fused_kernel<<<grid, block>>>(x, w, out);
}

// round 4
// speedup vs baseline: 2.6643x; 1.1980x over previous
#include <cuda_runtime.h>

// Problem constants
#define CAP_A   32
#define CAP_B   32
#define KK      3
#define PSIZE   16
#define STRIDE  2
#define OH      15
#define OW      15
#define NBATCH  2
#define NPOS    (NBATCH*OH*OW)   // 450
#define KKA     (KK*KK*CAP_A)    // 288
#define EPS_SQ  1e-8f
#define CPT     9                // capsules per thread (one warp per (n,j))
#define FULL    0xffffffffu

// Butterfly vector-exchange reduction: 32 lanes each hold t[0..15];
// afterwards lane l holds the lane-sum of component (l & 15).
// 16 + 8 + 4 + 2 + 1 = 31 shuffles.
__device__ __forceinline__ void vec_reduce16(float t[16], int lane) {
#pragma unroll
    for (int k = 0; k < 16; k++)
        t[k] += __shfl_xor_sync(FULL, t[k], 16);
    {
        const bool hi = lane & 8;
#pragma unroll
        for (int k = 0; k < 8; k++) {
            float keep = hi ? t[k + 8] : t[k];
            float send = hi ? t[k]     : t[k + 8];
            t[k] = keep + __shfl_xor_sync(FULL, send, 8);
        }
    }
    {
        const bool hi = lane & 4;
#pragma unroll
        for (int k = 0; k < 4; k++) {
            float keep = hi ? t[k + 4] : t[k];
            float send = hi ? t[k]     : t[k + 4];
            t[k] = keep + __shfl_xor_sync(FULL, send, 4);
        }
    }
    {
        const bool hi = lane & 2;
#pragma unroll
        for (int k = 0; k < 2; k++) {
            float keep = hi ? t[k + 2] : t[k];
            float send = hi ? t[k]     : t[k + 2];
            t[k] = keep + __shfl_xor_sync(FULL, send, 2);
        }
    }
    {
        const bool hi = lane & 1;
        float keep = hi ? t[1] : t[0];
        float send = hi ? t[0] : t[1];
        t[0] = keep + __shfl_xor_sync(FULL, send, 1);
    }
}

// Squash: input s = pooled component (lane&15); returns p likewise.
// Lanes 0..15 and 16..31 hold duplicate copies, so a 4-step butterfly
// over offsets 8,4,2,1 yields the full 16-component norm on every lane.
__device__ __forceinline__ float squash16(float s) {
    float n2 = s * s;
#pragma unroll
    for (int off = 8; off >= 1; off >>= 1)
        n2 += __shfl_xor_sync(FULL, n2, off);
    return s * (n2 / (1.f + n2) * rsqrtf(n2 + EPS_SQ));
}

__global__ __launch_bounds__(32) void caps_warp_kernel(
    const float* __restrict__ x,     // (2, 32, 32, 512)
    const float* __restrict__ w,     // (288, 32, 4, 4)
    float* __restrict__ out)         // (2, 15, 15, 512)
{
    const int bid = blockIdx.x;
    const int j   = bid & 31;
    const int n   = bid >> 5;
    const int b   = n / (OH * OW);
    const int rem = n % (OH * OW);
    const int oy  = rem / OW;
    const int ox  = rem % OW;

    const int lane = threadIdx.x;    // = a (input capsule type)

    // Thread owns i_c = c*32 + lane, c = ky*3 + kx.
    const float* xbase = x + ((size_t)((b * 32 + oy * STRIDE) * 32
                                       + ox * STRIDE) * 512 + lane * PSIZE);
    const float* wbase = w + ((size_t)(lane * CAP_B) + j) * PSIZE;

    float v[CPT][16];
#pragma unroll
    for (int c = 0; c < CPT; c++) {
        const int ky = c / 3, kx = c % 3;
        const float* xp = xbase + (size_t)(ky * 32 + kx) * 512;
        const float* wp = wbase + (size_t)c * 32 * CAP_B * PSIZE;
        float xm[16], wm[16];
#pragma unroll
        for (int t4 = 0; t4 < 4; t4++) {
            reinterpret_cast<float4*>(xm)[t4] = reinterpret_cast<const float4*>(xp)[t4];
            reinterpret_cast<float4*>(wm)[t4] = reinterpret_cast<const float4*>(wp)[t4];
        }
#pragma unroll
        for (int p = 0; p < 4; p++)
#pragma unroll
            for (int q = 0; q < 4; q++) {
                float acc = 0.f;
#pragma unroll
                for (int r = 0; r < 4; r++)
                    acc = fmaf(xm[p * 4 + r], wm[r * 4 + q], acc);
                v[c][p * 4 + q] = acc;
            }
    }

    float logit[CPT];
#pragma unroll
    for (int c = 0; c < CPT; c++) logit[c] = 0.f;

    float t[16];
    float pval;   // component (lane&15) of current p

    // ---- iteration 0: logits all zero -> r = 1/288 exactly ----
#pragma unroll
    for (int q = 0; q < 16; q++) {
        float s = v[0][q];
#pragma unroll
        for (int c = 1; c < CPT; c++) s += v[c][q];
        t[q] = s;
    }
    vec_reduce16(t, lane);
    pval = squash16(t[0] * (1.0f / (float)KKA));

    // agreement: logit_c += v_c . p
    {
        float pq[16];
#pragma unroll
        for (int q = 0; q < 16; q++) pq[q] = __shfl_sync(FULL, pval, q);
#pragma unroll
        for (int c = 0; c < CPT; c++) {
            float d = 0.f;
#pragma unroll
            for (int q = 0; q < 16; q++) d = fmaf(v[c][q], pq[q], d);
            logit[c] += d;
        }
    }

    // ---- iterations 1..2 ----
#pragma unroll
    for (int it = 1; it < 3; it++) {
        // softmax over all 288 logits (9 per thread, warp-reduced)
        float m = logit[0];
#pragma unroll
        for (int c = 1; c < CPT; c++) m = fmaxf(m, logit[c]);
#pragma unroll
        for (int off = 16; off >= 1; off >>= 1)
            m = fmaxf(m, __shfl_xor_sync(FULL, m, off));
        float e[CPT], z = 0.f;
#pragma unroll
        for (int c = 0; c < CPT; c++) { e[c] = __expf(logit[c] - m); z += e[c]; }
#pragma unroll
        for (int off = 16; off >= 1; off >>= 1)
            z += __shfl_xor_sync(FULL, z, off);
        const float rZ = __frcp_rn(z);

        // pool with weights e_c (scale by 1/Z after the reduction)
#pragma unroll
        for (int q = 0; q < 16; q++) {
            float s = e[0] * v[0][q];
#pragma unroll
            for (int c = 1; c < CPT; c++) s = fmaf(e[c], v[c][q], s);
            t[q] = s;
        }
        vec_reduce16(t, lane);
        pval = squash16(t[0] * rZ);

        if (it < 2) {
            float pq[16];
#pragma unroll
            for (int q = 0; q < 16; q++) pq[q] = __shfl_sync(FULL, pval, q);
#pragma unroll
            for (int c = 0; c < CPT; c++) {
                float d = 0.f;
#pragma unroll
                for (int q = 0; q < 16; q++) d = fmaf(v[c][q], pq[q], d);
                logit[c] += d;
            }
        }
    }

    // ---- output: lanes 0..15 hold p[0..15] ----
    if (lane < 16)
        out[(size_t)n * (CAP_B * PSIZE) + j * PSIZE + lane] = pval;
}

extern "C" void kernel_launch(void* const* d_in, const int* in_sizes, int n_in,
                              void* d_out, int out_size) {
    (void)in_sizes; (void)n_in; (void)out_size;
    const float* x = (const float*)d_in[0];
    const float* w = (const float*)d_in[1];
    float* out = (float*)d_out;

    dim3 grid(NPOS * CAP_B);   // 14400 warps, one per (n, j)
    dim3 block(32);
    caps_warp_kernel<<<grid, block>>>(x, w, out);
}